// round 5
// baseline (speedup 1.0000x reference)
#include <cuda_runtime.h>
#include <cstdint>
#include <math.h>

// Problem constants
#define BB   64
#define TT   256
#define DD   512
#define HH   1024
#define GG   4096   // 4*H
#define NCTA2 128   // persistent recurrent kernel grid size

// ---------------- device scratch (static allocation; no cudaMalloc allowed) ---
__device__ float g_gates[(size_t)TT * BB * GG];   // 268 MB: precomputed x@W_ih^T + biases
__device__ float g_h[BB * HH];
__device__ float g_c[BB * HH];
__device__ float g_gbuf[BB * GG];                 // per-step gate buffer
__device__ int   g_perm[BB];                      // batch order sorted by length desc
__device__ int   g_act[TT];                       // # active rows at step t
__device__ int   g_is64;                          // tokens/lengths are int64?
__device__ unsigned g_cnt = 0;                    // grid barrier counter
__device__ unsigned g_gen = 0;                    // grid barrier generation (monotone)

// ---------------- grid barrier (sense via monotone generation) ----------------
__device__ __forceinline__ void grid_barrier(unsigned& gen)
{
    __syncthreads();
    gen++;
    if (threadIdx.x == 0) {
        __threadfence();
        unsigned prev = atomicAdd(&g_cnt, 1u);
        if (prev == NCTA2 - 1) {
            atomicExch(&g_cnt, 0u);
            __threadfence();
            atomicExch(&g_gen, gen);
        } else {
            while (*((volatile unsigned*)&g_gen) < gen) { }
            __threadfence();
        }
    }
    __syncthreads();
}

// ---------------- prep: detect int width, sort batches by length desc ---------
__global__ void k_prep(const int* __restrict__ len32)
{
    // lengths >= 1 always. If int64 layout, l32[1] is the high word of
    // lengths[0] (== 0). If int32 layout, l32[1] = lengths[1] >= 1.
    int is64 = (len32[1] == 0) ? 1 : 0;
    g_is64 = is64;

    int perm[BB];
    int len[BB];
    for (int i = 0; i < BB; i++) {
        perm[i] = i;
        len[i]  = is64 ? len32[2 * i] : len32[i];   // values < 2^31: low word ok
    }
    // selection sort, descending by length
    for (int i = 0; i < BB; i++) {
        int best = i;
        for (int j = i + 1; j < BB; j++)
            if (len[j] > len[best]) best = j;
        int tl = len[i];  len[i]  = len[best];  len[best]  = tl;
        int tp = perm[i]; perm[i] = perm[best]; perm[best] = tp;
    }
    for (int i = 0; i < BB; i++) g_perm[i] = perm[i];
    for (int t = 0; t < TT; t++) {
        int cnt = 0;
        for (int i = 0; i < BB; i++) if (len[i] > t) cnt++;
        g_act[t] = cnt;
    }
}

// ---------------- phase 1: gates_x[t][i][n] = emb[tok] @ W_ih^T + b_ih + b_hh --
// CTA: 64 rows (one t, sorted batch order) x 64 cols. 256 threads, 4x4 micro,
// k-tile 16, double-buffered smem.
__global__ __launch_bounds__(256, 1) void k_input_gemm(
    const int*   __restrict__ tok32,
    const float* __restrict__ emb,
    const float* __restrict__ W_ih,
    const float* __restrict__ b_ih,
    const float* __restrict__ b_hh)
{
    const int t    = blockIdx.y;
    const int n0   = blockIdx.x * 64;
    const int Mact = g_act[t];
    if (Mact == 0) return;

    __shared__ __align__(16) float Xs[2][16][68];
    __shared__ __align__(16) float Ws[2][16][68];
    __shared__ int s_tok[BB];

    const int tid = threadIdx.x;
    if (tid < BB) {
        int b = g_perm[tid];
        size_t off = (size_t)b * TT + t;
        s_tok[tid] = g_is64 ? tok32[2 * off] : tok32[off];
    }
    __syncthreads();

    const int tx = tid & 15;
    const int ty = tid >> 4;
    const int m0 = ty * 4;
    const bool rowact = (m0 < Mact);

    float acc[4][4];
#pragma unroll
    for (int r = 0; r < 4; r++)
#pragma unroll
        for (int c = 0; c < 4; c++) acc[r][c] = 0.f;

    int lm[4], lk[4];
#pragma unroll
    for (int v = 0; v < 4; v++) { int e = tid + 256 * v; lm[v] = e >> 4; lk[v] = e & 15; }

    float xr[4], wr[4];
#pragma unroll
    for (int v = 0; v < 4; v++) {
        xr[v] = (lm[v] < Mact) ? emb[(size_t)s_tok[lm[v]] * DD + lk[v]] : 0.f;
        wr[v] = W_ih[(size_t)(n0 + lm[v]) * DD + lk[v]];
    }
#pragma unroll
    for (int v = 0; v < 4; v++) { Xs[0][lk[v]][lm[v]] = xr[v]; Ws[0][lk[v]][lm[v]] = wr[v]; }
    __syncthreads();

    const int NKT = DD / 16;  // 32
    for (int kt = 0; kt < NKT; kt++) {
        const int p = kt & 1;
        if (kt + 1 < NKT) {
            const int k0 = (kt + 1) * 16;
#pragma unroll
            for (int v = 0; v < 4; v++) {
                xr[v] = (lm[v] < Mact) ? emb[(size_t)s_tok[lm[v]] * DD + k0 + lk[v]] : 0.f;
                wr[v] = W_ih[(size_t)(n0 + lm[v]) * DD + k0 + lk[v]];
            }
        }
        if (rowact) {
#pragma unroll
            for (int kk = 0; kk < 16; kk++) {
                float4 a = *(const float4*)&Xs[p][kk][m0];
                float4 b = *(const float4*)&Ws[p][kk][tx * 4];
                acc[0][0] += a.x * b.x; acc[0][1] += a.x * b.y; acc[0][2] += a.x * b.z; acc[0][3] += a.x * b.w;
                acc[1][0] += a.y * b.x; acc[1][1] += a.y * b.y; acc[1][2] += a.y * b.z; acc[1][3] += a.y * b.w;
                acc[2][0] += a.z * b.x; acc[2][1] += a.z * b.y; acc[2][2] += a.z * b.z; acc[2][3] += a.z * b.w;
                acc[3][0] += a.w * b.x; acc[3][1] += a.w * b.y; acc[3][2] += a.w * b.z; acc[3][3] += a.w * b.w;
            }
        }
        if (kt + 1 < NKT) {
            const int q = (kt + 1) & 1;
#pragma unroll
            for (int v = 0; v < 4; v++) { Xs[q][lk[v]][lm[v]] = xr[v]; Ws[q][lk[v]][lm[v]] = wr[v]; }
            __syncthreads();
        }
    }

    if (rowact) {
        const int n = n0 + tx * 4;
        float bx = b_ih[n + 0] + b_hh[n + 0];
        float by = b_ih[n + 1] + b_hh[n + 1];
        float bz = b_ih[n + 2] + b_hh[n + 2];
        float bw = b_ih[n + 3] + b_hh[n + 3];
#pragma unroll
        for (int r = 0; r < 4; r++) {
            int m = m0 + r;
            if (m < Mact) {
                float4 o = make_float4(acc[r][0] + bx, acc[r][1] + by,
                                       acc[r][2] + bz, acc[r][3] + bw);
                *(float4*)&g_gates[((size_t)t * BB + m) * GG + n] = o;
            }
        }
    }
}

// ---------------- phase 2: persistent recurrent kernel ------------------------
// 128 CTAs x 256 threads. Each CTA owns a 32-column slice of the 4096 gate
// columns. Per step: gbuf = gates_x[t] + h @ W_hh^T (64x32 tile, K=1024,
// double-buffered smem, 4x2 micro), grid barrier, elementwise LSTM update,
// grid barrier. Cross-CTA global reads use __ldcg (L1 is not coherent).
__global__ __launch_bounds__(256, 1) void k_recurrent(
    const float* __restrict__ W_hh,
    float*       __restrict__ out)
{
    __shared__ __align__(16) float hs[2][32][68];
    __shared__ __align__(16) float Wsh[2][32][34];
    __shared__ int s_act[TT];
    __shared__ int s_perm[BB];
    __shared__ unsigned s_base;

    const int tid = threadIdx.x;
    const int cta = blockIdx.x;
    const int n0  = cta * 32;

    if (tid < TT) s_act[tid] = g_act[tid];
    if (tid < BB) s_perm[tid] = g_perm[tid];
    if (tid == 0) s_base = *((volatile unsigned*)&g_gen);

    // zero h, c (mapping idx -> cta is fixed; g_c stays CTA-private for L1)
    for (int idx = cta * 256 + tid; idx < BB * HH; idx += NCTA2 * 256) {
        g_h[idx] = 0.f;
        g_c[idx] = 0.f;
    }
    __syncthreads();
    unsigned gen = s_base;
    grid_barrier(gen);   // h/c zeroed + visible everywhere

    const int tx = tid & 15;
    const int ty = tid >> 4;
    const int m0 = ty * 4;
    const int j0 = tx * 2;

    for (int t = 0; t < TT; t++) {
        const int Mact = s_act[t];
        if (Mact == 0) break;            // act[] non-increasing: consistent break
        const bool rowact = (m0 < Mact);

        float acc[4][2];
#pragma unroll
        for (int r = 0; r < 4; r++) { acc[r][0] = 0.f; acc[r][1] = 0.f; }

        float hr[8], wr2[4];
#pragma unroll
        for (int v = 0; v < 8; v++) {
            int e = tid + 256 * v; int m = e >> 5; int kk = e & 31;
            hr[v] = (m < Mact) ? __ldcg(&g_h[m * HH + kk]) : 0.f;
        }
#pragma unroll
        for (int v = 0; v < 4; v++) {
            int e = tid + 256 * v; int j = e >> 5; int kk = e & 31;
            wr2[v] = W_hh[(size_t)(n0 + j) * HH + kk];
        }
#pragma unroll
        for (int v = 0; v < 8; v++) { int e = tid + 256 * v; hs[0][e & 31][e >> 5] = hr[v]; }
#pragma unroll
        for (int v = 0; v < 4; v++) { int e = tid + 256 * v; Wsh[0][e & 31][e >> 5] = wr2[v]; }
        __syncthreads();

        const int NKT = HH / 32;  // 32
        for (int kt = 0; kt < NKT; kt++) {
            const int p = kt & 1;
            if (kt + 1 < NKT) {
                const int k0 = (kt + 1) * 32;
#pragma unroll
                for (int v = 0; v < 8; v++) {
                    int e = tid + 256 * v; int m = e >> 5; int kk = e & 31;
                    hr[v] = (m < Mact) ? __ldcg(&g_h[m * HH + k0 + kk]) : 0.f;
                }
#pragma unroll
                for (int v = 0; v < 4; v++) {
                    int e = tid + 256 * v; int j = e >> 5; int kk = e & 31;
                    wr2[v] = W_hh[(size_t)(n0 + j) * HH + k0 + kk];
                }
            }
            if (rowact) {
#pragma unroll
                for (int kk = 0; kk < 32; kk++) {
                    float4 a = *(const float4*)&hs[p][kk][m0];
                    float2 b = *(const float2*)&Wsh[p][kk][j0];
                    acc[0][0] += a.x * b.x; acc[0][1] += a.x * b.y;
                    acc[1][0] += a.y * b.x; acc[1][1] += a.y * b.y;
                    acc[2][0] += a.z * b.x; acc[2][1] += a.z * b.y;
                    acc[3][0] += a.w * b.x; acc[3][1] += a.w * b.y;
                }
            }
            if (kt + 1 < NKT) {
                const int q = (kt + 1) & 1;
#pragma unroll
                for (int v = 0; v < 8; v++) { int e = tid + 256 * v; hs[q][e & 31][e >> 5] = hr[v]; }
#pragma unroll
                for (int v = 0; v < 4; v++) { int e = tid + 256 * v; Wsh[q][e & 31][e >> 5] = wr2[v]; }
                __syncthreads();
            }
        }

        if (rowact) {
#pragma unroll
            for (int r = 0; r < 4; r++) {
                int m = m0 + r;
                if (m < Mact) {
                    size_t gidx = ((size_t)t * BB + m) * GG + n0 + j0;
                    float2 gx = *(const float2*)&g_gates[gidx];
                    float2 o  = make_float2(acc[r][0] + gx.x, acc[r][1] + gx.y);
                    *(float2*)&g_gbuf[m * GG + n0 + j0] = o;
                }
            }
        }
        grid_barrier(gen);

        // elementwise LSTM update (idx -> cta mapping fixed: g_c CTA-private)
        for (int idx = cta * 256 + tid; idx < Mact * HH; idx += NCTA2 * 256) {
            int i  = idx >> 10;
            int hc = idx & (HH - 1);
            float ig = __ldcg(&g_gbuf[i * GG + hc]);
            float fg = __ldcg(&g_gbuf[i * GG + HH + hc]);
            float gg = __ldcg(&g_gbuf[i * GG + 2 * HH + hc]);
            float og = __ldcg(&g_gbuf[i * GG + 3 * HH + hc]);
            float is = 1.f / (1.f + expf(-ig));
            float fs = 1.f / (1.f + expf(-fg));
            float gt = tanhf(gg);
            float os = 1.f / (1.f + expf(-og));
            float cn = fs * g_c[idx] + is * gt;
            g_c[idx] = cn;
            g_h[idx] = os * tanhf(cn);
        }
        grid_barrier(gen);
    }

    // scatter h back to original batch order (same idx mapping as the updates,
    // so g_h[idx] was written by this CTA — plain load is safe)
    for (int idx = cta * 256 + tid; idx < BB * HH; idx += NCTA2 * 256) {
        int i  = idx >> 10;
        int hc = idx & (HH - 1);
        out[(size_t)s_perm[i] * HH + hc] = g_h[idx];
    }
}

// ---------------- launch -------------------------------------------------------
extern "C" void kernel_launch(void* const* d_in, const int* in_sizes, int n_in,
                              void* d_out, int out_size)
{
    const int*   tokens  = (const int*)  d_in[0];  // int32 or int64 (autodetected)
    const int*   lengths = (const int*)  d_in[1];
    const float* emb     = (const float*)d_in[2];
    const float* W_ih    = (const float*)d_in[3];
    const float* W_hh    = (const float*)d_in[4];
    const float* b_ih    = (const float*)d_in[5];
    const float* b_hh    = (const float*)d_in[6];
    float* out = (float*)d_out;

    k_prep<<<1, 1>>>(lengths);

    dim3 g1(GG / 64, TT);
    k_input_gemm<<<g1, 256>>>(tokens, emb, W_ih, b_ih, b_hh);

    k_recurrent<<<NCTA2, 256>>>(W_hh, out);
}

// round 6
// speedup vs baseline: 1.0034x; 1.0034x over previous
#include <cuda_runtime.h>
#include <cstdint>
#include <math.h>

// Problem constants
#define BB   64
#define TT   256
#define DD   512
#define HH   1024
#define GG   4096   // 4*H
#define NCTA2 128   // persistent recurrent kernel grid size

// ---------------- device scratch (static allocation; no cudaMalloc allowed) ---
__device__ float g_gates[(size_t)TT * BB * GG];   // 268 MB: precomputed x@W_ih^T + biases
__device__ float g_h[BB * HH];
__device__ float g_c[BB * HH];
__device__ float g_gbuf[BB * GG];                 // per-step gate buffer
__device__ int   g_perm[BB];                      // batch order sorted by length desc
__device__ int   g_act[TT];                       // # active rows at step t
__device__ int   g_is64;                          // tokens/lengths are int64?
__device__ unsigned g_cnt = 0;                    // grid barrier counter
__device__ unsigned g_gen = 0;                    // grid barrier generation (monotone)

// ---------------- grid barrier (sense via monotone generation) ----------------
__device__ __forceinline__ void grid_barrier(unsigned& gen)
{
    __syncthreads();
    gen++;
    if (threadIdx.x == 0) {
        __threadfence();
        unsigned prev = atomicAdd(&g_cnt, 1u);
        if (prev == NCTA2 - 1) {
            atomicExch(&g_cnt, 0u);
            __threadfence();
            atomicExch(&g_gen, gen);
        } else {
            while (*((volatile unsigned*)&g_gen) < gen) { }
            __threadfence();
        }
    }
    __syncthreads();
}

// ---------------- prep: detect int width, sort batches by length desc ---------
__global__ void k_prep(const int* __restrict__ len32)
{
    // lengths >= 1 always. If int64 layout, l32[1] is the high word of
    // lengths[0] (== 0). If int32 layout, l32[1] = lengths[1] >= 1.
    int is64 = (len32[1] == 0) ? 1 : 0;
    g_is64 = is64;

    int perm[BB];
    int len[BB];
    for (int i = 0; i < BB; i++) {
        perm[i] = i;
        len[i]  = is64 ? len32[2 * i] : len32[i];   // values < 2^31: low word ok
    }
    // selection sort, descending by length
    for (int i = 0; i < BB; i++) {
        int best = i;
        for (int j = i + 1; j < BB; j++)
            if (len[j] > len[best]) best = j;
        int tl = len[i];  len[i]  = len[best];  len[best]  = tl;
        int tp = perm[i]; perm[i] = perm[best]; perm[best] = tp;
    }
    for (int i = 0; i < BB; i++) g_perm[i] = perm[i];
    for (int t = 0; t < TT; t++) {
        int cnt = 0;
        for (int i = 0; i < BB; i++) if (len[i] > t) cnt++;
        g_act[t] = cnt;
    }
}

// ---------------- phase 1: gates_x[t][i][n] = emb[tok] @ W_ih^T + b_ih + b_hh --
// CTA: 64 rows (one t, sorted batch order) x 64 cols. 256 threads, 4x4 micro,
// k-tile 16, double-buffered smem.
__global__ __launch_bounds__(256, 1) void k_input_gemm(
    const int*   __restrict__ tok32,
    const float* __restrict__ emb,
    const float* __restrict__ W_ih,
    const float* __restrict__ b_ih,
    const float* __restrict__ b_hh)
{
    const int t    = blockIdx.y;
    const int n0   = blockIdx.x * 64;
    const int Mact = g_act[t];
    if (Mact == 0) return;

    __shared__ __align__(16) float Xs[2][16][68];
    __shared__ __align__(16) float Ws[2][16][68];
    __shared__ int s_tok[BB];

    const int tid = threadIdx.x;
    if (tid < BB) {
        int b = g_perm[tid];
        size_t off = (size_t)b * TT + t;
        s_tok[tid] = g_is64 ? tok32[2 * off] : tok32[off];
    }
    __syncthreads();

    const int tx = tid & 15;
    const int ty = tid >> 4;
    const int m0 = ty * 4;
    const bool rowact = (m0 < Mact);

    float acc[4][4];
#pragma unroll
    for (int r = 0; r < 4; r++)
#pragma unroll
        for (int c = 0; c < 4; c++) acc[r][c] = 0.f;

    int lm[4], lk[4];
#pragma unroll
    for (int v = 0; v < 4; v++) { int e = tid + 256 * v; lm[v] = e >> 4; lk[v] = e & 15; }

    float xr[4], wr[4];
#pragma unroll
    for (int v = 0; v < 4; v++) {
        xr[v] = (lm[v] < Mact) ? emb[(size_t)s_tok[lm[v]] * DD + lk[v]] : 0.f;
        wr[v] = W_ih[(size_t)(n0 + lm[v]) * DD + lk[v]];
    }
#pragma unroll
    for (int v = 0; v < 4; v++) { Xs[0][lk[v]][lm[v]] = xr[v]; Ws[0][lk[v]][lm[v]] = wr[v]; }
    __syncthreads();

    const int NKT = DD / 16;  // 32
    for (int kt = 0; kt < NKT; kt++) {
        const int p = kt & 1;
        if (kt + 1 < NKT) {
            const int k0 = (kt + 1) * 16;
#pragma unroll
            for (int v = 0; v < 4; v++) {
                xr[v] = (lm[v] < Mact) ? emb[(size_t)s_tok[lm[v]] * DD + k0 + lk[v]] : 0.f;
                wr[v] = W_ih[(size_t)(n0 + lm[v]) * DD + k0 + lk[v]];
            }
        }
        if (rowact) {
#pragma unroll
            for (int kk = 0; kk < 16; kk++) {
                float4 a = *(const float4*)&Xs[p][kk][m0];
                float4 b = *(const float4*)&Ws[p][kk][tx * 4];
                acc[0][0] += a.x * b.x; acc[0][1] += a.x * b.y; acc[0][2] += a.x * b.z; acc[0][3] += a.x * b.w;
                acc[1][0] += a.y * b.x; acc[1][1] += a.y * b.y; acc[1][2] += a.y * b.z; acc[1][3] += a.y * b.w;
                acc[2][0] += a.z * b.x; acc[2][1] += a.z * b.y; acc[2][2] += a.z * b.z; acc[2][3] += a.z * b.w;
                acc[3][0] += a.w * b.x; acc[3][1] += a.w * b.y; acc[3][2] += a.w * b.z; acc[3][3] += a.w * b.w;
            }
        }
        if (kt + 1 < NKT) {
            const int q = (kt + 1) & 1;
#pragma unroll
            for (int v = 0; v < 4; v++) { Xs[q][lk[v]][lm[v]] = xr[v]; Ws[q][lk[v]][lm[v]] = wr[v]; }
            __syncthreads();
        }
    }

    if (rowact) {
        const int n = n0 + tx * 4;
        float bx = b_ih[n + 0] + b_hh[n + 0];
        float by = b_ih[n + 1] + b_hh[n + 1];
        float bz = b_ih[n + 2] + b_hh[n + 2];
        float bw = b_ih[n + 3] + b_hh[n + 3];
#pragma unroll
        for (int r = 0; r < 4; r++) {
            int m = m0 + r;
            if (m < Mact) {
                float4 o = make_float4(acc[r][0] + bx, acc[r][1] + by,
                                       acc[r][2] + bz, acc[r][3] + bw);
                *(float4*)&g_gates[((size_t)t * BB + m) * GG + n] = o;
            }
        }
    }
}

// ---------------- phase 2: persistent recurrent kernel ------------------------
// 128 CTAs x 256 threads. Each CTA owns a 32-column slice of the 4096 gate
// columns. Per step: gbuf = gates_x[t] + h @ W_hh^T (64x32 tile, K=1024,
// double-buffered smem, 4x2 micro), grid barrier, elementwise LSTM update,
// grid barrier. Cross-CTA global reads use __ldcg (L1 is not coherent).
__global__ __launch_bounds__(256, 1) void k_recurrent(
    const float* __restrict__ W_hh,
    float*       __restrict__ out)
{
    __shared__ __align__(16) float hs[2][32][68];
    __shared__ __align__(16) float Wsh[2][32][34];
    __shared__ int s_act[TT];
    __shared__ int s_perm[BB];
    __shared__ unsigned s_base;

    const int tid = threadIdx.x;
    const int cta = blockIdx.x;
    const int n0  = cta * 32;

    if (tid < TT) s_act[tid] = g_act[tid];
    if (tid < BB) s_perm[tid] = g_perm[tid];
    if (tid == 0) s_base = *((volatile unsigned*)&g_gen);

    // zero h, c (mapping idx -> cta is fixed; g_c stays CTA-private for L1)
    for (int idx = cta * 256 + tid; idx < BB * HH; idx += NCTA2 * 256) {
        g_h[idx] = 0.f;
        g_c[idx] = 0.f;
    }
    __syncthreads();
    unsigned gen = s_base;
    grid_barrier(gen);   // h/c zeroed + visible everywhere

    const int tx = tid & 15;
    const int ty = tid >> 4;
    const int m0 = ty * 4;
    const int j0 = tx * 2;

    for (int t = 0; t < TT; t++) {
        const int Mact = s_act[t];
        if (Mact == 0) break;            // act[] non-increasing: consistent break
        const bool rowact = (m0 < Mact);

        float acc[4][2];
#pragma unroll
        for (int r = 0; r < 4; r++) { acc[r][0] = 0.f; acc[r][1] = 0.f; }

        float hr[8], wr2[4];
#pragma unroll
        for (int v = 0; v < 8; v++) {
            int e = tid + 256 * v; int m = e >> 5; int kk = e & 31;
            hr[v] = (m < Mact) ? __ldcg(&g_h[m * HH + kk]) : 0.f;
        }
#pragma unroll
        for (int v = 0; v < 4; v++) {
            int e = tid + 256 * v; int j = e >> 5; int kk = e & 31;
            wr2[v] = W_hh[(size_t)(n0 + j) * HH + kk];
        }
#pragma unroll
        for (int v = 0; v < 8; v++) { int e = tid + 256 * v; hs[0][e & 31][e >> 5] = hr[v]; }
#pragma unroll
        for (int v = 0; v < 4; v++) { int e = tid + 256 * v; Wsh[0][e & 31][e >> 5] = wr2[v]; }
        __syncthreads();

        const int NKT = HH / 32;  // 32
        for (int kt = 0; kt < NKT; kt++) {
            const int p = kt & 1;
            if (kt + 1 < NKT) {
                const int k0 = (kt + 1) * 32;
#pragma unroll
                for (int v = 0; v < 8; v++) {
                    int e = tid + 256 * v; int m = e >> 5; int kk = e & 31;
                    hr[v] = (m < Mact) ? __ldcg(&g_h[m * HH + k0 + kk]) : 0.f;
                }
#pragma unroll
                for (int v = 0; v < 4; v++) {
                    int e = tid + 256 * v; int j = e >> 5; int kk = e & 31;
                    wr2[v] = W_hh[(size_t)(n0 + j) * HH + k0 + kk];
                }
            }
            if (rowact) {
#pragma unroll
                for (int kk = 0; kk < 32; kk++) {
                    float4 a = *(const float4*)&hs[p][kk][m0];
                    float2 b = *(const float2*)&Wsh[p][kk][j0];
                    acc[0][0] += a.x * b.x; acc[0][1] += a.x * b.y;
                    acc[1][0] += a.y * b.x; acc[1][1] += a.y * b.y;
                    acc[2][0] += a.z * b.x; acc[2][1] += a.z * b.y;
                    acc[3][0] += a.w * b.x; acc[3][1] += a.w * b.y;
                }
            }
            if (kt + 1 < NKT) {
                const int q = (kt + 1) & 1;
#pragma unroll
                for (int v = 0; v < 8; v++) { int e = tid + 256 * v; hs[q][e & 31][e >> 5] = hr[v]; }
#pragma unroll
                for (int v = 0; v < 4; v++) { int e = tid + 256 * v; Wsh[q][e & 31][e >> 5] = wr2[v]; }
                __syncthreads();
            }
        }

        if (rowact) {
#pragma unroll
            for (int r = 0; r < 4; r++) {
                int m = m0 + r;
                if (m < Mact) {
                    size_t gidx = ((size_t)t * BB + m) * GG + n0 + j0;
                    float2 gx = *(const float2*)&g_gates[gidx];
                    float2 o  = make_float2(acc[r][0] + gx.x, acc[r][1] + gx.y);
                    *(float2*)&g_gbuf[m * GG + n0 + j0] = o;
                }
            }
        }
        grid_barrier(gen);

        // elementwise LSTM update (idx -> cta mapping fixed: g_c CTA-private)
        for (int idx = cta * 256 + tid; idx < Mact * HH; idx += NCTA2 * 256) {
            int i  = idx >> 10;
            int hc = idx & (HH - 1);
            float ig = __ldcg(&g_gbuf[i * GG + hc]);
            float fg = __ldcg(&g_gbuf[i * GG + HH + hc]);
            float gg = __ldcg(&g_gbuf[i * GG + 2 * HH + hc]);
            float og = __ldcg(&g_gbuf[i * GG + 3 * HH + hc]);
            float is = 1.f / (1.f + expf(-ig));
            float fs = 1.f / (1.f + expf(-fg));
            float gt = tanhf(gg);
            float os = 1.f / (1.f + expf(-og));
            float cn = fs * g_c[idx] + is * gt;
            g_c[idx] = cn;
            g_h[idx] = os * tanhf(cn);
        }
        grid_barrier(gen);
    }

    // scatter h back to original batch order (same idx mapping as the updates,
    // so g_h[idx] was written by this CTA — plain load is safe)
    for (int idx = cta * 256 + tid; idx < BB * HH; idx += NCTA2 * 256) {
        int i  = idx >> 10;
        int hc = idx & (HH - 1);
        out[(size_t)s_perm[i] * HH + hc] = g_h[idx];
    }
}

// ---------------- launch -------------------------------------------------------
extern "C" void kernel_launch(void* const* d_in, const int* in_sizes, int n_in,
                              void* d_out, int out_size)
{
    const int*   tokens  = (const int*)  d_in[0];  // int32 or int64 (autodetected)
    const int*   lengths = (const int*)  d_in[1];
    const float* emb     = (const float*)d_in[2];
    const float* W_ih    = (const float*)d_in[3];
    const float* W_hh    = (const float*)d_in[4];
    const float* b_ih    = (const float*)d_in[5];
    const float* b_hh    = (const float*)d_in[6];
    float* out = (float*)d_out;

    k_prep<<<1, 1>>>(lengths);

    dim3 g1(GG / 64, TT);
    k_input_gemm<<<g1, 256>>>(tokens, emb, W_ih, b_ih, b_hh);

    k_recurrent<<<NCTA2, 256>>>(W_hh, out);
}

// round 7
// speedup vs baseline: 1.9242x; 1.9176x over previous
#include <cuda_runtime.h>
#include <cuda_bf16.h>
#include <cstdint>
#include <math.h>

// Problem constants
#define BB   64
#define TT   256
#define DD   512
#define HH   1024
#define GG   4096   // 4*H
#define NCTA2 128   // persistent recurrent kernel grid size

// ---------------- device scratch (static; no cudaMalloc allowed) --------------
__device__ float         g_gates[(size_t)TT * BB * GG]; // x@W_ih^T + b_ih + b_hh
__device__ __nv_bfloat16 g_hh[2][BB * HH];              // h hi plane, double buffered
__device__ __nv_bfloat16 g_hl[2][BB * HH];              // h lo plane
__device__ float         g_hout[BB * HH];               // last-active h (fp32)
__device__ int           g_perm[BB];
__device__ int           g_act[TT];
__device__ int           g_is64;
__device__ unsigned      g_cnt = 0;
__device__ unsigned      g_gen = 0;

// ---------------- grid barrier (monotone generation) --------------------------
__device__ __forceinline__ void grid_barrier(unsigned& gen)
{
    __syncthreads();
    gen++;
    if (threadIdx.x == 0) {
        __threadfence();
        unsigned prev = atomicAdd(&g_cnt, 1u);
        if (prev == NCTA2 - 1) {
            atomicExch(&g_cnt, 0u);
            __threadfence();
            atomicExch(&g_gen, gen);
        } else {
            while (*((volatile unsigned*)&g_gen) < gen) { }
            __threadfence();
        }
    }
    __syncthreads();
}

// ---------------- bf16 hi/lo split + pack helpers ------------------------------
__device__ __forceinline__ unsigned packbf(__nv_bfloat16 a, __nv_bfloat16 b) {
    return ((unsigned)__bfloat16_as_ushort(b) << 16) | (unsigned)__bfloat16_as_ushort(a);
}
__device__ __forceinline__ void split_pack(float x, float y, unsigned& hi, unsigned& lo) {
    __nv_bfloat16 hx = __float2bfloat16(x);
    __nv_bfloat16 hy = __float2bfloat16(y);
    hi = packbf(hx, hy);
    lo = packbf(__float2bfloat16(x - __bfloat162float(hx)),
                __float2bfloat16(y - __bfloat162float(hy)));
}

// ---------------- ldmatrix / mma wrappers --------------------------------------
__device__ __forceinline__ void ldsm4(unsigned* r, const __nv_bfloat16* p) {
    unsigned a = (unsigned)__cvta_generic_to_shared((void*)p);
    asm volatile("ldmatrix.sync.aligned.m8n8.x4.shared.b16 {%0,%1,%2,%3}, [%4];"
                 : "=r"(r[0]), "=r"(r[1]), "=r"(r[2]), "=r"(r[3]) : "r"(a));
}
__device__ __forceinline__ void mma16816(float* c, const unsigned* a,
                                         unsigned b0, unsigned b1) {
    asm volatile("mma.sync.aligned.m16n8k16.row.col.f32.bf16.bf16.f32 "
                 "{%0,%1,%2,%3},{%4,%5,%6,%7},{%8,%9},{%0,%1,%2,%3};"
                 : "+f"(c[0]), "+f"(c[1]), "+f"(c[2]), "+f"(c[3])
                 : "r"(a[0]), "r"(a[1]), "r"(a[2]), "r"(a[3]), "r"(b0), "r"(b1));
}

// ---------------- prep: parallel rank sort by length (desc, stable) ------------
__global__ void k_prep(const int* __restrict__ len32)
{
    __shared__ int slen[BB];
    const int tid = threadIdx.x;
    const int is64 = (len32[1] == 0) ? 1 : 0;   // lengths >= 1 always
    if (tid == 0) g_is64 = is64;
    if (tid < BB) slen[tid] = is64 ? len32[2 * tid] : len32[tid];
    __syncthreads();
    if (tid < BB) {
        int li = slen[tid], r = 0;
        for (int j = 0; j < BB; j++) {
            int lj = slen[j];
            r += (lj > li) || (lj == li && j < tid);
        }
        g_perm[r] = tid;
    }
    if (tid < TT) {
        int cnt = 0;
        for (int j = 0; j < BB; j++) cnt += (slen[j] > tid);
        g_act[tid] = cnt;
    }
}

// ---------------- phase 1: gates_x = emb[tok] @ W_ih^T + b_ih + b_hh -----------
// grid (128 n-blocks of 32 cols, 256 t), 256 threads. Warp tile 16x16 (4mw x 2nw).
// bf16 3-term mma; A (gathered embeddings) and W_ih staged hi/lo per 64-k chunk.
__global__ __launch_bounds__(256) void k_input_gemm(
    const int*   __restrict__ tok32,
    const float* __restrict__ emb,
    const float* __restrict__ W_ih,
    const float* __restrict__ b_ih,
    const float* __restrict__ b_hh)
{
    const int t = blockIdx.y;
    const int Mact = g_act[t];
    if (Mact == 0) return;
    const int n0 = blockIdx.x * 32;

    __shared__ __align__(16) __nv_bfloat16 AsH[64 * 72], AsL[64 * 72];
    __shared__ __align__(16) __nv_bfloat16 WsH[32 * 72], WsL[32 * 72];
    __shared__ int s_tok[BB];

    const int tid = threadIdx.x;
    if (tid < BB) {
        int b = g_perm[tid];
        size_t off = (size_t)b * TT + t;
        s_tok[tid] = g_is64 ? tok32[2 * off] : tok32[off];
    }
    __syncthreads();

    const int wid = tid >> 5, lane = tid & 31;
    const int mw = wid >> 1, nw = wid & 1;
    const int aRow = mw * 16 + (lane & 15);
    const int aCo  = (lane >> 4) << 3;
    const int bRow = nw * 16 + ((lane >> 4) << 3) + (lane & 7);
    const int bCo  = ((lane >> 3) & 1) << 3;
    const bool wact = (mw * 16 < Mact);

    float acc[2][4] = {{0.f,0.f,0.f,0.f},{0.f,0.f,0.f,0.f}};

    for (int kc = 0; kc < 8; kc++) {           // 8 chunks of 64 k
        if (kc) __syncthreads();
        // stage A: 64 rows x 16 float4
#pragma unroll
        for (int v = 0; v < 4; v++) {
            int e = tid + 256 * v;
            int row = e >> 4, c4 = e & 15;
            if (row < Mact) {
                float4 x = *(const float4*)&emb[(size_t)s_tok[row] * DD + kc * 64 + c4 * 4];
                unsigned h0, l0, h1, l1;
                split_pack(x.x, x.y, h0, l0);
                split_pack(x.z, x.w, h1, l1);
                unsigned idx = row * 36 + c4 * 2;
                ((unsigned*)AsH)[idx]     = h0; ((unsigned*)AsH)[idx + 1] = h1;
                ((unsigned*)AsL)[idx]     = l0; ((unsigned*)AsL)[idx + 1] = l1;
            }
        }
        // stage W: 32 rows x 16 float4
#pragma unroll
        for (int v = 0; v < 2; v++) {
            int e = tid + 256 * v;
            int row = e >> 4, c4 = e & 15;
            float4 w = *(const float4*)&W_ih[(size_t)(n0 + row) * DD + kc * 64 + c4 * 4];
            unsigned h0, l0, h1, l1;
            split_pack(w.x, w.y, h0, l0);
            split_pack(w.z, w.w, h1, l1);
            unsigned idx = row * 36 + c4 * 2;
            ((unsigned*)WsH)[idx]     = h0; ((unsigned*)WsH)[idx + 1] = h1;
            ((unsigned*)WsL)[idx]     = l0; ((unsigned*)WsL)[idx + 1] = l1;
        }
        __syncthreads();
        if (wact) {
#pragma unroll
            for (int ks = 0; ks < 4; ks++) {
                unsigned aH[4], aL[4], bH[4], bL[4];
                int c = ks * 16;
                ldsm4(aH, AsH + aRow * 72 + c + aCo);
                ldsm4(aL, AsL + aRow * 72 + c + aCo);
                ldsm4(bH, WsH + bRow * 72 + c + bCo);
                ldsm4(bL, WsL + bRow * 72 + c + bCo);
                mma16816(acc[0], aH, bH[0], bH[1]);
                mma16816(acc[1], aH, bH[2], bH[3]);
                mma16816(acc[0], aH, bL[0], bL[1]);
                mma16816(acc[1], aH, bL[2], bL[3]);
                mma16816(acc[0], aL, bH[0], bH[1]);
                mma16816(acc[1], aL, bH[2], bH[3]);
            }
        }
    }

    if (!wact) return;
    const int r0 = mw * 16 + (lane >> 2);
    const int jj = 2 * (lane & 3);
    float* go = g_gates + ((size_t)t * BB) * GG;
#pragma unroll
    for (int nt = 0; nt < 2; nt++) {
        int col = n0 + nw * 16 + nt * 8 + jj;
        float2 b0 = *(const float2*)&b_ih[col];
        float2 b1 = *(const float2*)&b_hh[col];
        float bx = b0.x + b1.x, by = b0.y + b1.y;
        if (r0 < Mact)
            *(float2*)(go + (size_t)r0 * GG + col) =
                make_float2(acc[nt][0] + bx, acc[nt][1] + by);
        if (r0 + 8 < Mact)
            *(float2*)(go + (size_t)(r0 + 8) * GG + col) =
                make_float2(acc[nt][2] + bx, acc[nt][3] + by);
    }
}

// ---------------- phase 2: persistent recurrent kernel -------------------------
// 128 CTAs x 256 threads. CTA owns 8 h-cols x all 4 gates (32 W_hh rows) so the
// LSTM update is CTA-local; h double-buffered in global bf16 hi/lo planes
// => ONE grid barrier per step. W slice resident in smem hi/lo (132 KB).
__global__ __launch_bounds__(256, 1) void k_recurrent(
    const float* __restrict__ W_hh,
    float*       __restrict__ out)
{
    extern __shared__ char dyn[];
    __nv_bfloat16* WsH = (__nv_bfloat16*)(dyn);            //  66048 B (32 x 1032)
    __nv_bfloat16* WsL = (__nv_bfloat16*)(dyn + 66048);    //  66048 B
    __nv_bfloat16* AhH = (__nv_bfloat16*)(dyn + 132096);   //  17408 B (64 x 136)
    __nv_bfloat16* AhL = (__nv_bfloat16*)(dyn + 149504);   //  17408 B
    float*         Gs  = (float*)(dyn + 166912);           //   8192 B (4 x 64 x 8)
    float*         Cs  = (float*)(dyn + 175104);           //   2048 B (64 x 8)
    int*         s_act = (int*)(dyn + 177152);             //   1024 B
    int*        s_perm = (int*)(dyn + 178176);             //    256 B
    __shared__ unsigned s_base;

    const int tid = threadIdx.x;
    const int cta = blockIdx.x;
    const int hc0 = cta * 8;
    const int wid = tid >> 5, lane = tid & 31;
    const int mw = wid >> 1, nw = wid & 1;

    if (tid < TT) s_act[tid] = g_act[tid];
    if (tid < BB) s_perm[tid] = g_perm[tid];
    if (tid == 0) s_base = *((volatile unsigned*)&g_gen);
    for (int i = tid; i < BB * 8; i += 256) Cs[i] = 0.f;

    // stage W_hh slice hi/lo (rows (q>>3)*H + hc0 + (q&7), q = 0..31)
    for (int v = 0; v < 32; v++) {
        int e = tid + 256 * v;         // 8192 float4s = 32 rows x 256
        int q = e >> 8, c4 = e & 255;
        int gr = (q >> 3) * HH + hc0 + (q & 7);
        float4 w = *(const float4*)&W_hh[(size_t)gr * HH + c4 * 4];
        unsigned h0, l0, h1, l1;
        split_pack(w.x, w.y, h0, l0);
        split_pack(w.z, w.w, h1, l1);
        unsigned idx = q * 516 + c4 * 2;
        ((unsigned*)WsH)[idx]     = h0; ((unsigned*)WsH)[idx + 1] = h1;
        ((unsigned*)WsL)[idx]     = l0; ((unsigned*)WsL)[idx + 1] = l1;
    }

    // zero h parity 0 (h0 = 0); exactly one u32 per thread chip-wide
    {
        int i = cta * 256 + tid;
        ((unsigned*)g_hh[0])[i] = 0u;
        ((unsigned*)g_hl[0])[i] = 0u;
    }
    __syncthreads();
    unsigned gen = s_base;
    grid_barrier(gen);

    const int aRow = mw * 16 + (lane & 15);
    const int aCo  = (lane >> 4) << 3;
    const int bRow = nw * 16 + ((lane >> 4) << 3) + (lane & 7);
    const int bCo  = ((lane >> 3) & 1) << 3;
    const int r0   = mw * 16 + (lane >> 2);
    const int jj   = 2 * (lane & 3);

    for (int t = 0; t < TT; t++) {
        const int Mact = s_act[t];
        if (Mact == 0) break;            // non-increasing: consistent everywhere
        const int p = t & 1;
        const bool wact = (mw * 16 < Mact);

        // prefetch gates_x for this warp's c-frag (overlaps with whole GEMM)
        float gx[2][4];
        const float* gbase = g_gates + ((size_t)t * BB) * GG;
#pragma unroll
        for (int nt = 0; nt < 2; nt++) {
            int gate = nw * 2 + nt;
            int gcol = gate * HH + hc0 + jj;
            gx[nt][0] = gx[nt][1] = gx[nt][2] = gx[nt][3] = 0.f;
            if (r0 < Mact) {
                float2 v = *(const float2*)(gbase + (size_t)r0 * GG + gcol);
                gx[nt][0] = v.x; gx[nt][1] = v.y;
            }
            if (r0 + 8 < Mact) {
                float2 v = *(const float2*)(gbase + (size_t)(r0 + 8) * GG + gcol);
                gx[nt][2] = v.x; gx[nt][3] = v.y;
            }
        }

        float acc[2][4] = {{0.f,0.f,0.f,0.f},{0.f,0.f,0.f,0.f}};
        const unsigned* hhu = (const unsigned*)g_hh[p];
        const unsigned* hlu = (const unsigned*)g_hl[p];

        for (int kc = 0; kc < 8; kc++) {       // 8 chunks of 128 k
            __syncthreads();                   // protect smem from prior reads
#pragma unroll
            for (int v = 0; v < 16; v++) {     // stage h chunk (rows < Mact)
                int e = tid + 256 * v;
                int row = e >> 6, c = e & 63;
                if (row < Mact) {
                    int src = row * 512 + kc * 64 + c;   // u32 index (2 bf16)
                    ((unsigned*)AhH)[row * 68 + c] = __ldcg(hhu + src);
                    ((unsigned*)AhL)[row * 68 + c] = __ldcg(hlu + src);
                }
            }
            __syncthreads();
            if (wact) {
#pragma unroll
                for (int ks = 0; ks < 8; ks++) {
                    unsigned aH[4], aL[4], bH[4], bL[4];
                    int ac = ks * 16 + aCo;
                    int wc = kc * 128 + ks * 16 + bCo;
                    ldsm4(aH, AhH + aRow * 136 + ac);
                    ldsm4(aL, AhL + aRow * 136 + ac);
                    ldsm4(bH, WsH + bRow * 1032 + wc);
                    ldsm4(bL, WsL + bRow * 1032 + wc);
                    mma16816(acc[0], aH, bH[0], bH[1]);
                    mma16816(acc[1], aH, bH[2], bH[3]);
                    mma16816(acc[0], aH, bL[0], bL[1]);
                    mma16816(acc[1], aH, bL[2], bL[3]);
                    mma16816(acc[0], aL, bH[0], bH[1]);
                    mma16816(acc[1], aL, bH[2], bH[3]);
                }
            }
        }

        // gates -> smem exchange (gate = nw*2 + nt)
#pragma unroll
        for (int nt = 0; nt < 2; nt++) {
            int gate = nw * 2 + nt;
            Gs[(gate * 64 + r0) * 8 + jj]         = acc[nt][0] + gx[nt][0];
            Gs[(gate * 64 + r0) * 8 + jj + 1]     = acc[nt][1] + gx[nt][1];
            Gs[(gate * 64 + r0 + 8) * 8 + jj]     = acc[nt][2] + gx[nt][2];
            Gs[(gate * 64 + r0 + 8) * 8 + jj + 1] = acc[nt][3] + gx[nt][3];
        }
        __syncthreads();

        // CTA-local LSTM update; write h_new hi/lo to next parity + fp32 out buf
        const int pn = p ^ 1;
        for (int idx = tid; idx < Mact * 8; idx += 256) {
            int m = idx >> 3, j = idx & 7;
            float ig = Gs[(0 * 64 + m) * 8 + j];
            float fg = Gs[(1 * 64 + m) * 8 + j];
            float gg = Gs[(2 * 64 + m) * 8 + j];
            float og = Gs[(3 * 64 + m) * 8 + j];
            float is = 1.f / (1.f + expf(-ig));
            float fs = 1.f / (1.f + expf(-fg));
            float gt = tanhf(gg);
            float os = 1.f / (1.f + expf(-og));
            float cn = fs * Cs[idx] + is * gt;
            Cs[idx] = cn;
            float hn = os * tanhf(cn);
            int col = hc0 + j;
            g_hout[(size_t)m * HH + col] = hn;
            __nv_bfloat16 hh = __float2bfloat16(hn);
            g_hh[pn][m * HH + col] = hh;
            g_hl[pn][m * HH + col] = __float2bfloat16(hn - __bfloat162float(hh));
        }
        grid_barrier(gen);
    }

    // scatter back to original batch order (CTA-owned cols only)
    for (int idx = tid; idx < BB * 8; idx += 256) {
        int m = idx >> 3, j = idx & 7;
        out[(size_t)s_perm[m] * HH + hc0 + j] = g_hout[(size_t)m * HH + hc0 + j];
    }
}

// ---------------- launch --------------------------------------------------------
#define SMEM2 178432

extern "C" void kernel_launch(void* const* d_in, const int* in_sizes, int n_in,
                              void* d_out, int out_size)
{
    const int*   tokens  = (const int*)  d_in[0];  // int32/int64 autodetected
    const int*   lengths = (const int*)  d_in[1];
    const float* emb     = (const float*)d_in[2];
    const float* W_ih    = (const float*)d_in[3];
    const float* W_hh    = (const float*)d_in[4];
    const float* b_ih    = (const float*)d_in[5];
    const float* b_hh    = (const float*)d_in[6];
    float* out = (float*)d_out;

    cudaFuncSetAttribute(k_recurrent,
                         cudaFuncAttributeMaxDynamicSharedMemorySize, SMEM2);

    k_prep<<<1, 256>>>(lengths);

    dim3 g1(GG / 32, TT);   // (128, 256)
    k_input_gemm<<<g1, 256>>>(tokens, emb, W_ih, b_ih, b_hh);

    k_recurrent<<<NCTA2, 256, SMEM2>>>(W_hh, out);
}

// round 10
// speedup vs baseline: 2.1146x; 1.0990x over previous
#include <cuda_runtime.h>
#include <cuda_bf16.h>
#include <cstdint>
#include <math.h>

// Problem constants
#define BB   64
#define TT   256
#define DD   512
#define HH   1024
#define GG   4096   // 4*H
#define NCTA2 128   // persistent recurrent kernel grid size

// ---------------- device scratch (static; no cudaMalloc allowed) --------------
__device__ float    g_gates[(size_t)TT * BB * GG];          // x@W_ih^T + biases
__device__ __align__(16) unsigned g_xh[(size_t)TT * BB * (DD/2)];  // X hi plane (u32 = 2 bf16)
__device__ __align__(16) unsigned g_xl[(size_t)TT * BB * (DD/2)];  // X lo plane
__device__ __align__(16) unsigned g_wih_h[GG * (DD/2)];     // W_ih hi plane
__device__ __align__(16) unsigned g_wih_l[GG * (DD/2)];     // W_ih lo plane
__device__ __align__(16) __nv_bfloat16 g_hh[2][BB * HH];    // h hi, double buffered
__device__ __align__(16) __nv_bfloat16 g_hl[2][BB * HH];    // h lo
__device__ float    g_hout[BB * HH];                        // last-active h (fp32)
__device__ int      g_perm[BB];
__device__ int      g_act[TT];
__device__ int      g_is64;
__device__ unsigned g_cnt = 0;                              // counter barrier
__device__ unsigned g_gen = 0;                              // barrier generation

// ---------------- small asm helpers --------------------------------------------
__device__ __forceinline__ void cp16(unsigned saddr, const void* g) {
    asm volatile("cp.async.cg.shared.global [%0], [%1], 16;"
                 :: "r"(saddr), "l"(g) : "memory");
}
__device__ __forceinline__ void cp_commit() {
    asm volatile("cp.async.commit_group;" ::: "memory");
}
template<int N> __device__ __forceinline__ void cp_wait() {
    asm volatile("cp.async.wait_group %0;" :: "n"(N) : "memory");
}
__device__ __forceinline__ void ldsm4(unsigned* r, const __nv_bfloat16* p) {
    unsigned a = (unsigned)__cvta_generic_to_shared((void*)p);
    asm volatile("ldmatrix.sync.aligned.m8n8.x4.shared.b16 {%0,%1,%2,%3}, [%4];"
                 : "=r"(r[0]), "=r"(r[1]), "=r"(r[2]), "=r"(r[3]) : "r"(a));
}
__device__ __forceinline__ void mma16816(float* c, const unsigned* a,
                                         unsigned b0, unsigned b1) {
    asm volatile("mma.sync.aligned.m16n8k16.row.col.f32.bf16.bf16.f32 "
                 "{%0,%1,%2,%3},{%4,%5,%6,%7},{%8,%9},{%0,%1,%2,%3};"
                 : "+f"(c[0]), "+f"(c[1]), "+f"(c[2]), "+f"(c[3])
                 : "r"(a[0]), "r"(a[1]), "r"(a[2]), "r"(a[3]), "r"(b0), "r"(b1));
}

// ---------------- bf16 hi/lo split + pack --------------------------------------
__device__ __forceinline__ unsigned packbf(__nv_bfloat16 a, __nv_bfloat16 b) {
    return ((unsigned)__bfloat16_as_ushort(b) << 16) | (unsigned)__bfloat16_as_ushort(a);
}
__device__ __forceinline__ void split_pack(float x, float y, unsigned& hi, unsigned& lo) {
    __nv_bfloat16 hx = __float2bfloat16(x);
    __nv_bfloat16 hy = __float2bfloat16(y);
    hi = packbf(hx, hy);
    lo = packbf(__float2bfloat16(x - __bfloat162float(hx)),
                __float2bfloat16(y - __bfloat162float(hy)));
}

// ---------------- grid barrier (monotone generation, counter) ------------------
// (round-7 proven implementation)
__device__ __forceinline__ void grid_barrier(unsigned& gen)
{
    __syncthreads();
    gen++;
    if (threadIdx.x == 0) {
        __threadfence();
        unsigned prev = atomicAdd(&g_cnt, 1u);
        if (prev == NCTA2 - 1) {
            atomicExch(&g_cnt, 0u);
            __threadfence();
            atomicExch(&g_gen, gen);
        } else {
            while (*((volatile unsigned*)&g_gen) < gen) { }
            __threadfence();
        }
    }
    __syncthreads();
}

// ---------------- prep: parallel rank sort by length (desc, stable) ------------
__global__ void k_prep(const int* __restrict__ len32)
{
    __shared__ int slen[BB];
    const int tid = threadIdx.x;
    const int is64 = (len32[1] == 0) ? 1 : 0;   // lengths >= 1 always
    if (tid == 0) g_is64 = is64;
    if (tid < BB) slen[tid] = is64 ? len32[2 * tid] : len32[tid];
    __syncthreads();
    if (tid < BB) {
        int li = slen[tid], r = 0;
        for (int j = 0; j < BB; j++) {
            int lj = slen[j];
            r += (lj > li) || (lj == li && j < tid);
        }
        g_perm[r] = tid;
    }
    if (tid < TT) {
        int cnt = 0;
        for (int j = 0; j < BB; j++) cnt += (slen[j] > tid);
        g_act[tid] = cnt;
    }
}

// ---------------- pre-split X: gather emb rows, hi/lo bf16, zeros if inactive --
__global__ __launch_bounds__(256) void k_embed(const int* __restrict__ tok32,
                                               const float* __restrict__ emb)
{
    const int tid = threadIdx.x;
    const int r = blockIdx.x * 8 + (tid >> 5);   // global row = t*64 + m
    const int lane = tid & 31;
    const int t = r >> 6, m = r & 63;
    const bool act = (m < g_act[t]);
    int tok = 0;
    if (act) {
        size_t off = (size_t)g_perm[m] * TT + t;
        tok = g_is64 ? tok32[2 * off] : tok32[off];
    }
#pragma unroll
    for (int i = 0; i < 4; i++) {
        int k = i * 128 + lane * 4;
        uint2 hi = make_uint2(0u, 0u), lo = make_uint2(0u, 0u);
        if (act) {
            float4 x = *(const float4*)&emb[(size_t)tok * DD + k];
            split_pack(x.x, x.y, hi.x, lo.x);
            split_pack(x.z, x.w, hi.y, lo.y);
        }
        ((uint2*)g_xh)[(size_t)r * 128 + i * 32 + lane] = hi;
        ((uint2*)g_xl)[(size_t)r * 128 + i * 32 + lane] = lo;
    }
}

// ---------------- pre-split W_ih into bf16 hi/lo planes -------------------------
__global__ __launch_bounds__(256) void k_wsplit(const float* __restrict__ W)
{
    const int tid = threadIdx.x;
    const int r = blockIdx.x * 8 + (tid >> 5);   // row in [0, 4096)
    const int lane = tid & 31;
#pragma unroll
    for (int i = 0; i < 4; i++) {
        int k = i * 128 + lane * 4;
        float4 w = *(const float4*)&W[(size_t)r * DD + k];
        uint2 hi, lo;
        split_pack(w.x, w.y, hi.x, lo.x);
        split_pack(w.z, w.w, hi.y, lo.y);
        ((uint2*)g_wih_h)[(size_t)r * 128 + i * 32 + lane] = hi;
        ((uint2*)g_wih_l)[(size_t)r * 128 + i * 32 + lane] = lo;
    }
}

// ---------------- phase 1: dense bf16 GEMM gates_x = X @ W_ih^T + biases --------
// grid (32 n-blocks of 128, 256 t), 512 threads (16 warps: 4 mw x 4 nw).
// Warp tile M16 x N32. cp.async double-buffered staging from pre-split planes.
// Buffer layout (55296 B each): Ah@0 (9216), Al@9216 (9216), Wh@18432 (18432),
//                               Wl@36864 (18432).
#define SMEM1 110592
__global__ __launch_bounds__(512) void k_input_gemm(
    const float* __restrict__ b_ih,
    const float* __restrict__ b_hh)
{
    const int t = blockIdx.y;
    const int Mact = g_act[t];
    if (Mact == 0) return;
    const int n0 = blockIdx.x * 128;

    extern __shared__ char dyn1[];
    const unsigned sbase = (unsigned)__cvta_generic_to_shared(dyn1);

    const int tid = threadIdx.x, wid = tid >> 5, lane = tid & 31;
    const int mw = wid & 3, nw = wid >> 2;
    const bool wact = (mw * 16 < Mact);

    const int aRow = mw * 16 + (lane & 15);
    const int aCo  = (lane >> 4) << 3;
    const int bR   = ((lane >> 4) << 3) + (lane & 7);
    const int bCo  = ((lane >> 3) & 1) << 3;

    float acc[4][4];
#pragma unroll
    for (int i = 0; i < 4; i++)
#pragma unroll
        for (int j = 0; j < 4; j++) acc[i][j] = 0.f;

    // per-kc staging: A 1024 16B-chunks (2 planes x 64 rows x 8), W 2048
    auto stage = [&](int kc, int b) {
        unsigned base = sbase + b * 55296;
#pragma unroll
        for (int v = 0; v < 2; v++) {           // A
            int e = tid + 512 * v;              // < 1024
            int plane = e >> 9, rr = (e >> 3) & 63, ch = e & 7;
            const unsigned* src = (plane ? g_xl : g_xh) +
                ((size_t)(t * 64 + rr) * 256 + kc * 32 + ch * 4);
            cp16(base + plane * 9216 + rr * 144 + ch * 16, src);
        }
#pragma unroll
        for (int v = 0; v < 4; v++) {           // W (plane stride 18432)
            int e = tid + 512 * v;              // < 2048
            int plane = e >> 10, rr = (e >> 3) & 127, ch = e & 7;
            const unsigned* src = (plane ? g_wih_l : g_wih_h) +
                ((size_t)(n0 + rr) * 256 + kc * 32 + ch * 4);
            cp16(base + 18432 + plane * 18432 + rr * 144 + ch * 16, src);
        }
    };

    stage(0, 0); cp_commit();

    for (int kc = 0; kc < 8; kc++) {            // 8 chunks of 64 k
        if (kc < 7) { stage(kc + 1, (kc + 1) & 1); cp_commit(); }
        if (kc < 7) cp_wait<1>(); else cp_wait<0>();
        __syncthreads();
        if (wact) {
            const char* buf = dyn1 + (kc & 1) * 55296;
            const __nv_bfloat16* Ah = (const __nv_bfloat16*)(buf);
            const __nv_bfloat16* Al = (const __nv_bfloat16*)(buf + 9216);
            const __nv_bfloat16* Wh = (const __nv_bfloat16*)(buf + 18432);
            const __nv_bfloat16* Wl = (const __nv_bfloat16*)(buf + 36864);
#pragma unroll
            for (int ks = 0; ks < 4; ks++) {
                unsigned aH[4], aL[4], bH0[4], bL0[4], bH1[4], bL1[4];
                int c = ks * 16;
                ldsm4(aH, Ah + aRow * 72 + c + aCo);
                ldsm4(aL, Al + aRow * 72 + c + aCo);
                int r0w = nw * 32 + bR;
                ldsm4(bH0, Wh + r0w * 72 + c + bCo);
                ldsm4(bL0, Wl + r0w * 72 + c + bCo);
                ldsm4(bH1, Wh + (r0w + 16) * 72 + c + bCo);
                ldsm4(bL1, Wl + (r0w + 16) * 72 + c + bCo);
                mma16816(acc[0], aH, bH0[0], bH0[1]);
                mma16816(acc[1], aH, bH0[2], bH0[3]);
                mma16816(acc[0], aH, bL0[0], bL0[1]);
                mma16816(acc[1], aH, bL0[2], bL0[3]);
                mma16816(acc[0], aL, bH0[0], bH0[1]);
                mma16816(acc[1], aL, bH0[2], bH0[3]);
                mma16816(acc[2], aH, bH1[0], bH1[1]);
                mma16816(acc[3], aH, bH1[2], bH1[3]);
                mma16816(acc[2], aH, bL1[0], bL1[1]);
                mma16816(acc[3], aH, bL1[2], bL1[3]);
                mma16816(acc[2], aL, bH1[0], bH1[1]);
                mma16816(acc[3], aL, bH1[2], bH1[3]);
            }
        }
        __syncthreads();
    }

    if (!wact) return;
    const int r0 = mw * 16 + (lane >> 2);
    const int jj = 2 * (lane & 3);
    float* go = g_gates + ((size_t)t * BB) * GG;
#pragma unroll
    for (int nt = 0; nt < 4; nt++) {
        int col = n0 + nw * 32 + nt * 8 + jj;
        float2 b0 = *(const float2*)&b_ih[col];
        float2 b1 = *(const float2*)&b_hh[col];
        float bx = b0.x + b1.x, by = b0.y + b1.y;
        if (r0 < Mact)
            *(float2*)(go + (size_t)r0 * GG + col) =
                make_float2(acc[nt][0] + bx, acc[nt][1] + by);
        if (r0 + 8 < Mact)
            *(float2*)(go + (size_t)(r0 + 8) * GG + col) =
                make_float2(acc[nt][2] + bx, acc[nt][3] + by);
    }
}

// ---------------- phase 2: persistent recurrent kernel (ROUND-7 PROVEN) --------
// 128 CTAs x 256 threads. CTA owns 8 h-cols x 4 gates; W slice resident in smem.
// h double-buffered in global bf16 hi/lo planes; __ldcg staging; counter
// barrier, ONE per step.
#define SMEM2 178432
__global__ __launch_bounds__(256, 1) void k_recurrent(
    const float* __restrict__ W_hh,
    float*       __restrict__ out)
{
    extern __shared__ char dyn[];
    __nv_bfloat16* WsH = (__nv_bfloat16*)(dyn);            //  66048 B (32 x 1032)
    __nv_bfloat16* WsL = (__nv_bfloat16*)(dyn + 66048);    //  66048 B
    __nv_bfloat16* AhH = (__nv_bfloat16*)(dyn + 132096);   //  17408 B (64 x 136)
    __nv_bfloat16* AhL = (__nv_bfloat16*)(dyn + 149504);   //  17408 B
    float*         Gs  = (float*)(dyn + 166912);           //   8192 B (4 x 64 x 8)
    float*         Cs  = (float*)(dyn + 175104);           //   2048 B (64 x 8)
    int*         s_act = (int*)(dyn + 177152);             //   1024 B
    int*        s_perm = (int*)(dyn + 178176);             //    256 B
    __shared__ unsigned s_base;

    const int tid = threadIdx.x;
    const int cta = blockIdx.x;
    const int hc0 = cta * 8;
    const int wid = tid >> 5, lane = tid & 31;
    const int mw = wid >> 1, nw = wid & 1;

    if (tid < TT) s_act[tid] = g_act[tid];
    if (tid < BB) s_perm[tid] = g_perm[tid];
    if (tid == 0) s_base = *((volatile unsigned*)&g_gen);
    for (int i = tid; i < BB * 8; i += 256) Cs[i] = 0.f;

    // stage W_hh slice hi/lo (rows (q>>3)*H + hc0 + (q&7), q = 0..31)
    for (int v = 0; v < 32; v++) {
        int e = tid + 256 * v;         // 8192 float4s = 32 rows x 256
        int q = e >> 8, c4 = e & 255;
        int gr = (q >> 3) * HH + hc0 + (q & 7);
        float4 w = *(const float4*)&W_hh[(size_t)gr * HH + c4 * 4];
        unsigned h0, l0, h1, l1;
        split_pack(w.x, w.y, h0, l0);
        split_pack(w.z, w.w, h1, l1);
        unsigned idx = q * 516 + c4 * 2;
        ((unsigned*)WsH)[idx]     = h0; ((unsigned*)WsH)[idx + 1] = h1;
        ((unsigned*)WsL)[idx]     = l0; ((unsigned*)WsL)[idx + 1] = l1;
    }

    // zero h parity 0; exactly one u32 per thread chip-wide per plane
    {
        int i = cta * 256 + tid;
        ((unsigned*)g_hh[0])[i] = 0u;
        ((unsigned*)g_hl[0])[i] = 0u;
    }
    __syncthreads();
    unsigned gen = s_base;
    grid_barrier(gen);   // h/c zeroed + visible everywhere

    const int aRow = mw * 16 + (lane & 15);
    const int aCo  = (lane >> 4) << 3;
    const int bRow = nw * 16 + ((lane >> 4) << 3) + (lane & 7);
    const int bCo  = ((lane >> 3) & 1) << 3;
    const int r0   = mw * 16 + (lane >> 2);
    const int jj   = 2 * (lane & 3);

    for (int t = 0; t < TT; t++) {
        const int Mact = s_act[t];
        if (Mact == 0) break;            // non-increasing: uniform across CTAs
        const int p = t & 1;
        const bool wact = (mw * 16 < Mact);

        // prefetch gates_x (overlaps whole GEMM)
        float gx[2][4];
        const float* gbase = g_gates + ((size_t)t * BB) * GG;
#pragma unroll
        for (int nt = 0; nt < 2; nt++) {
            int gate = nw * 2 + nt;
            int gcol = gate * HH + hc0 + jj;
            gx[nt][0] = gx[nt][1] = gx[nt][2] = gx[nt][3] = 0.f;
            if (r0 < Mact) {
                float2 v = *(const float2*)(gbase + (size_t)r0 * GG + gcol);
                gx[nt][0] = v.x; gx[nt][1] = v.y;
            }
            if (r0 + 8 < Mact) {
                float2 v = *(const float2*)(gbase + (size_t)(r0 + 8) * GG + gcol);
                gx[nt][2] = v.x; gx[nt][3] = v.y;
            }
        }

        float acc[2][4] = {{0.f,0.f,0.f,0.f},{0.f,0.f,0.f,0.f}};
        const unsigned* hhu = (const unsigned*)g_hh[p];
        const unsigned* hlu = (const unsigned*)g_hl[p];

        for (int kc = 0; kc < 8; kc++) {       // 8 chunks of 128 k
            __syncthreads();                   // protect smem from prior reads
#pragma unroll
            for (int v = 0; v < 16; v++) {     // stage h chunk (rows < Mact)
                int e = tid + 256 * v;
                int row = e >> 6, c = e & 63;
                if (row < Mact) {
                    int src = row * 512 + kc * 64 + c;   // u32 index (2 bf16)
                    ((unsigned*)AhH)[row * 68 + c] = __ldcg(hhu + src);
                    ((unsigned*)AhL)[row * 68 + c] = __ldcg(hlu + src);
                }
            }
            __syncthreads();
            if (wact) {
#pragma unroll
                for (int ks = 0; ks < 8; ks++) {
                    unsigned aH[4], aL[4], bH[4], bL[4];
                    int ac = ks * 16 + aCo;
                    int wc = kc * 128 + ks * 16 + bCo;
                    ldsm4(aH, AhH + aRow * 136 + ac);
                    ldsm4(aL, AhL + aRow * 136 + ac);
                    ldsm4(bH, WsH + bRow * 1032 + wc);
                    ldsm4(bL, WsL + bRow * 1032 + wc);
                    mma16816(acc[0], aH, bH[0], bH[1]);
                    mma16816(acc[1], aH, bH[2], bH[3]);
                    mma16816(acc[0], aH, bL[0], bL[1]);
                    mma16816(acc[1], aH, bL[2], bL[3]);
                    mma16816(acc[0], aL, bH[0], bH[1]);
                    mma16816(acc[1], aL, bH[2], bH[3]);
                }
            }
        }

        // gates -> smem exchange (gate = nw*2 + nt)
#pragma unroll
        for (int nt = 0; nt < 2; nt++) {
            int gate = nw * 2 + nt;
            Gs[(gate * 64 + r0) * 8 + jj]         = acc[nt][0] + gx[nt][0];
            Gs[(gate * 64 + r0) * 8 + jj + 1]     = acc[nt][1] + gx[nt][1];
            Gs[(gate * 64 + r0 + 8) * 8 + jj]     = acc[nt][2] + gx[nt][2];
            Gs[(gate * 64 + r0 + 8) * 8 + jj + 1] = acc[nt][3] + gx[nt][3];
        }
        __syncthreads();

        // CTA-local LSTM update; write h_new hi/lo to next parity
        const int pn = p ^ 1;
        for (int idx = tid; idx < Mact * 8; idx += 256) {
            int m = idx >> 3, j = idx & 7;
            float ig = Gs[(0 * 64 + m) * 8 + j];
            float fg = Gs[(1 * 64 + m) * 8 + j];
            float gg = Gs[(2 * 64 + m) * 8 + j];
            float og = Gs[(3 * 64 + m) * 8 + j];
            float is = 1.f / (1.f + expf(-ig));
            float fs = 1.f / (1.f + expf(-fg));
            float gt = tanhf(gg);
            float os = 1.f / (1.f + expf(-og));
            float cn = fs * Cs[idx] + is * gt;
            Cs[idx] = cn;
            float hn = os * tanhf(cn);
            int col = hc0 + j;
            g_hout[(size_t)m * HH + col] = hn;
            __nv_bfloat16 hh = __float2bfloat16(hn);
            g_hh[pn][m * HH + col] = hh;
            g_hl[pn][m * HH + col] = __float2bfloat16(hn - __bfloat162float(hh));
        }
        grid_barrier(gen);
    }

    // scatter back to original batch order (CTA-owned cols only)
    for (int idx = tid; idx < BB * 8; idx += 256) {
        int m = idx >> 3, j = idx & 7;
        out[(size_t)s_perm[m] * HH + hc0 + j] = g_hout[(size_t)m * HH + hc0 + j];
    }
}

// ---------------- launch --------------------------------------------------------
extern "C" void kernel_launch(void* const* d_in, const int* in_sizes, int n_in,
                              void* d_out, int out_size)
{
    const int*   tokens  = (const int*)  d_in[0];  // int32/int64 autodetected
    const int*   lengths = (const int*)  d_in[1];
    const float* emb     = (const float*)d_in[2];
    const float* W_ih    = (const float*)d_in[3];
    const float* W_hh    = (const float*)d_in[4];
    const float* b_ih    = (const float*)d_in[5];
    const float* b_hh    = (const float*)d_in[6];
    float* out = (float*)d_out;

    cudaFuncSetAttribute(k_input_gemm,
                         cudaFuncAttributeMaxDynamicSharedMemorySize, SMEM1);
    cudaFuncSetAttribute(k_recurrent,
                         cudaFuncAttributeMaxDynamicSharedMemorySize, SMEM2);

    k_prep<<<1, 256>>>(lengths);
    k_wsplit<<<GG / 8, 256>>>(W_ih);                 // 512 CTAs
    k_embed<<<TT * BB / 8, 256>>>(tokens, emb);      // 2048 CTAs

    dim3 g1(GG / 128, TT);                           // (32, 256)
    k_input_gemm<<<g1, 512, SMEM1>>>(b_ih, b_hh);

    k_recurrent<<<NCTA2, 256, SMEM2>>>(W_hh, out);
}

// round 11
// speedup vs baseline: 2.9232x; 1.3824x over previous
#include <cuda_runtime.h>
#include <cuda_bf16.h>
#include <cstdint>
#include <math.h>

// Problem constants
#define BB   64
#define TT   256
#define DD   512
#define HH   1024
#define GG   4096   // 4*H
#define NCTA2 128   // persistent recurrent kernel grid size

// ---------------- device scratch (static; no cudaMalloc allowed) --------------
__device__ float    g_gates[(size_t)TT * BB * GG];          // x@W_ih^T + biases
__device__ __align__(16) unsigned g_xh[(size_t)TT * BB * (DD/2)];  // X hi plane (u32 = 2 bf16)
__device__ __align__(16) unsigned g_xl[(size_t)TT * BB * (DD/2)];  // X lo plane
__device__ __align__(16) unsigned g_wih_h[GG * (DD/2)];     // W_ih hi plane
__device__ __align__(16) unsigned g_wih_l[GG * (DD/2)];     // W_ih lo plane
__device__ __align__(16) __nv_bfloat16 g_hh[2][BB * HH];    // h hi, double buffered
__device__ __align__(16) __nv_bfloat16 g_hl[2][BB * HH];    // h lo
__device__ float    g_hout[BB * HH];                        // last-active h (fp32)
__device__ int      g_perm[BB];
__device__ int      g_act[TT];
__device__ int      g_is64;
__device__ unsigned g_cnt8[8 * 64];                         // sub-counters, 256B apart
__device__ unsigned g_cnt = 0;                              // master counter
__device__ unsigned g_gen = 0;                              // barrier generation

// ---------------- small asm helpers --------------------------------------------
__device__ __forceinline__ void cp16(unsigned saddr, const void* g) {
    asm volatile("cp.async.cg.shared.global [%0], [%1], 16;"
                 :: "r"(saddr), "l"(g) : "memory");
}
__device__ __forceinline__ void cp_commit() {
    asm volatile("cp.async.commit_group;" ::: "memory");
}
template<int N> __device__ __forceinline__ void cp_wait() {
    asm volatile("cp.async.wait_group %0;" :: "n"(N) : "memory");
}
__device__ __forceinline__ uint4 ldcg4(const unsigned* p) {
    uint4 v;
    asm volatile("ld.global.cg.v4.u32 {%0,%1,%2,%3}, [%4];"
                 : "=r"(v.x), "=r"(v.y), "=r"(v.z), "=r"(v.w) : "l"(p) : "memory");
    return v;
}
__device__ __forceinline__ void ldsm4(unsigned* r, const __nv_bfloat16* p) {
    unsigned a = (unsigned)__cvta_generic_to_shared((void*)p);
    asm volatile("ldmatrix.sync.aligned.m8n8.x4.shared.b16 {%0,%1,%2,%3}, [%4];"
                 : "=r"(r[0]), "=r"(r[1]), "=r"(r[2]), "=r"(r[3]) : "r"(a));
}
__device__ __forceinline__ void mma16816(float* c, const unsigned* a,
                                         unsigned b0, unsigned b1) {
    asm volatile("mma.sync.aligned.m16n8k16.row.col.f32.bf16.bf16.f32 "
                 "{%0,%1,%2,%3},{%4,%5,%6,%7},{%8,%9},{%0,%1,%2,%3};"
                 : "+f"(c[0]), "+f"(c[1]), "+f"(c[2]), "+f"(c[3])
                 : "r"(a[0]), "r"(a[1]), "r"(a[2]), "r"(a[3]), "r"(b0), "r"(b1));
}

// ---------------- bf16 hi/lo split + pack --------------------------------------
__device__ __forceinline__ unsigned packbf(__nv_bfloat16 a, __nv_bfloat16 b) {
    return ((unsigned)__bfloat16_as_ushort(b) << 16) | (unsigned)__bfloat16_as_ushort(a);
}
__device__ __forceinline__ void split_pack(float x, float y, unsigned& hi, unsigned& lo) {
    __nv_bfloat16 hx = __float2bfloat16(x);
    __nv_bfloat16 hy = __float2bfloat16(y);
    hi = packbf(hx, hy);
    lo = packbf(__float2bfloat16(x - __bfloat162float(hx)),
                __float2bfloat16(y - __bfloat162float(hy)));
}

// ---------------- grid barrier (monotone generation, TREE counters) ------------
// Same protocol as the proven counter barrier, arrivals parallelized over 8
// sub-counters (256 B apart). All resets happen before g_gen is released, so
// no CTA can touch a counter while it is being reset. Replay-safe (counters
// return to 0; g_gen monotone, re-read as base at kernel start).
__device__ __forceinline__ void grid_barrier(unsigned& gen)
{
    __syncthreads();
    gen++;
    if (threadIdx.x == 0) {
        __threadfence();
        int grp = blockIdx.x & 7;
        unsigned prev = atomicAdd(&g_cnt8[grp * 64], 1u);
        bool released = false;
        if (prev == 15u) {                       // last of this 16-CTA group
            atomicExch(&g_cnt8[grp * 64], 0u);   // reset before master arrive
            unsigned p2 = atomicAdd(&g_cnt, 1u);
            if (p2 == 7u) {                      // last group
                atomicExch(&g_cnt, 0u);
                __threadfence();
                atomicExch(&g_gen, gen);
                released = true;
            }
        }
        if (!released) {
            while (*((volatile unsigned*)&g_gen) < gen) { }
            __threadfence();
        }
    }
    __syncthreads();
}

// ---------------- prep: parallel rank sort by length (desc, stable) ------------
__global__ void k_prep(const int* __restrict__ len32)
{
    __shared__ int slen[BB];
    const int tid = threadIdx.x;
    const int is64 = (len32[1] == 0) ? 1 : 0;   // lengths >= 1 always
    if (tid == 0) g_is64 = is64;
    if (tid < BB) slen[tid] = is64 ? len32[2 * tid] : len32[tid];
    __syncthreads();
    if (tid < BB) {
        int li = slen[tid], r = 0;
        for (int j = 0; j < BB; j++) {
            int lj = slen[j];
            r += (lj > li) || (lj == li && j < tid);
        }
        g_perm[r] = tid;
    }
    if (tid < TT) {
        int cnt = 0;
        for (int j = 0; j < BB; j++) cnt += (slen[j] > tid);
        g_act[tid] = cnt;
    }
}

// ---------------- pre-split X: gather emb rows, hi/lo bf16, zeros if inactive --
__global__ __launch_bounds__(256) void k_embed(const int* __restrict__ tok32,
                                               const float* __restrict__ emb)
{
    const int tid = threadIdx.x;
    const int r = blockIdx.x * 8 + (tid >> 5);   // global row = t*64 + m
    const int lane = tid & 31;
    const int t = r >> 6, m = r & 63;
    const bool act = (m < g_act[t]);
    int tok = 0;
    if (act) {
        size_t off = (size_t)g_perm[m] * TT + t;
        tok = g_is64 ? tok32[2 * off] : tok32[off];
    }
#pragma unroll
    for (int i = 0; i < 4; i++) {
        int k = i * 128 + lane * 4;
        uint2 hi = make_uint2(0u, 0u), lo = make_uint2(0u, 0u);
        if (act) {
            float4 x = *(const float4*)&emb[(size_t)tok * DD + k];
            split_pack(x.x, x.y, hi.x, lo.x);
            split_pack(x.z, x.w, hi.y, lo.y);
        }
        ((uint2*)g_xh)[(size_t)r * 128 + i * 32 + lane] = hi;
        ((uint2*)g_xl)[(size_t)r * 128 + i * 32 + lane] = lo;
    }
}

// ---------------- pre-split W_ih into bf16 hi/lo planes -------------------------
__global__ __launch_bounds__(256) void k_wsplit(const float* __restrict__ W)
{
    const int tid = threadIdx.x;
    const int r = blockIdx.x * 8 + (tid >> 5);   // row in [0, 4096)
    const int lane = tid & 31;
#pragma unroll
    for (int i = 0; i < 4; i++) {
        int k = i * 128 + lane * 4;
        float4 w = *(const float4*)&W[(size_t)r * DD + k];
        uint2 hi, lo;
        split_pack(w.x, w.y, hi.x, lo.x);
        split_pack(w.z, w.w, hi.y, lo.y);
        ((uint2*)g_wih_h)[(size_t)r * 128 + i * 32 + lane] = hi;
        ((uint2*)g_wih_l)[(size_t)r * 128 + i * 32 + lane] = lo;
    }
}

// ---------------- phase 1: dense bf16 GEMM gates_x = X @ W_ih^T + biases --------
// (unchanged from passing round-10 version)
#define SMEM1 110592
__global__ __launch_bounds__(512) void k_input_gemm(
    const float* __restrict__ b_ih,
    const float* __restrict__ b_hh)
{
    const int t = blockIdx.y;
    const int Mact = g_act[t];
    if (Mact == 0) return;
    const int n0 = blockIdx.x * 128;

    extern __shared__ char dyn1[];
    const unsigned sbase = (unsigned)__cvta_generic_to_shared(dyn1);

    const int tid = threadIdx.x, wid = tid >> 5, lane = tid & 31;
    const int mw = wid & 3, nw = wid >> 2;
    const bool wact = (mw * 16 < Mact);

    const int aRow = mw * 16 + (lane & 15);
    const int aCo  = (lane >> 4) << 3;
    const int bR   = ((lane >> 4) << 3) + (lane & 7);
    const int bCo  = ((lane >> 3) & 1) << 3;

    float acc[4][4];
#pragma unroll
    for (int i = 0; i < 4; i++)
#pragma unroll
        for (int j = 0; j < 4; j++) acc[i][j] = 0.f;

    auto stage = [&](int kc, int b) {
        unsigned base = sbase + b * 55296;
#pragma unroll
        for (int v = 0; v < 2; v++) {           // A
            int e = tid + 512 * v;              // < 1024
            int plane = e >> 9, rr = (e >> 3) & 63, ch = e & 7;
            const unsigned* src = (plane ? g_xl : g_xh) +
                ((size_t)(t * 64 + rr) * 256 + kc * 32 + ch * 4);
            cp16(base + plane * 9216 + rr * 144 + ch * 16, src);
        }
#pragma unroll
        for (int v = 0; v < 4; v++) {           // W (plane stride 18432)
            int e = tid + 512 * v;              // < 2048
            int plane = e >> 10, rr = (e >> 3) & 127, ch = e & 7;
            const unsigned* src = (plane ? g_wih_l : g_wih_h) +
                ((size_t)(n0 + rr) * 256 + kc * 32 + ch * 4);
            cp16(base + 18432 + plane * 18432 + rr * 144 + ch * 16, src);
        }
    };

    stage(0, 0); cp_commit();

    for (int kc = 0; kc < 8; kc++) {            // 8 chunks of 64 k
        if (kc < 7) { stage(kc + 1, (kc + 1) & 1); cp_commit(); }
        if (kc < 7) cp_wait<1>(); else cp_wait<0>();
        __syncthreads();
        if (wact) {
            const char* buf = dyn1 + (kc & 1) * 55296;
            const __nv_bfloat16* Ah = (const __nv_bfloat16*)(buf);
            const __nv_bfloat16* Al = (const __nv_bfloat16*)(buf + 9216);
            const __nv_bfloat16* Wh = (const __nv_bfloat16*)(buf + 18432);
            const __nv_bfloat16* Wl = (const __nv_bfloat16*)(buf + 36864);
#pragma unroll
            for (int ks = 0; ks < 4; ks++) {
                unsigned aH[4], aL[4], bH0[4], bL0[4], bH1[4], bL1[4];
                int c = ks * 16;
                ldsm4(aH, Ah + aRow * 72 + c + aCo);
                ldsm4(aL, Al + aRow * 72 + c + aCo);
                int r0w = nw * 32 + bR;
                ldsm4(bH0, Wh + r0w * 72 + c + bCo);
                ldsm4(bL0, Wl + r0w * 72 + c + bCo);
                ldsm4(bH1, Wh + (r0w + 16) * 72 + c + bCo);
                ldsm4(bL1, Wl + (r0w + 16) * 72 + c + bCo);
                mma16816(acc[0], aH, bH0[0], bH0[1]);
                mma16816(acc[1], aH, bH0[2], bH0[3]);
                mma16816(acc[0], aH, bL0[0], bL0[1]);
                mma16816(acc[1], aH, bL0[2], bL0[3]);
                mma16816(acc[0], aL, bH0[0], bH0[1]);
                mma16816(acc[1], aL, bH0[2], bH0[3]);
                mma16816(acc[2], aH, bH1[0], bH1[1]);
                mma16816(acc[3], aH, bH1[2], bH1[3]);
                mma16816(acc[2], aH, bL1[0], bL1[1]);
                mma16816(acc[3], aH, bL1[2], bL1[3]);
                mma16816(acc[2], aL, bH1[0], bH1[1]);
                mma16816(acc[3], aL, bH1[2], bH1[3]);
            }
        }
        __syncthreads();
    }

    if (!wact) return;
    const int r0 = mw * 16 + (lane >> 2);
    const int jj = 2 * (lane & 3);
    float* go = g_gates + ((size_t)t * BB) * GG;
#pragma unroll
    for (int nt = 0; nt < 4; nt++) {
        int col = n0 + nw * 32 + nt * 8 + jj;
        float2 b0 = *(const float2*)&b_ih[col];
        float2 b1 = *(const float2*)&b_hh[col];
        float bx = b0.x + b1.x, by = b0.y + b1.y;
        if (r0 < Mact)
            *(float2*)(go + (size_t)r0 * GG + col) =
                make_float2(acc[nt][0] + bx, acc[nt][1] + by);
        if (r0 + 8 < Mact)
            *(float2*)(go + (size_t)(r0 + 8) * GG + col) =
                make_float2(acc[nt][2] + bx, acc[nt][3] + by);
    }
}

// ---------------- phase 2: persistent recurrent kernel -------------------------
// 128 CTAs x 256 threads. CTA owns 8 h-cols x 4 gates; W slice resident in smem.
// h double-buffered in global bf16 hi/lo planes. Register-pipelined staging:
// chunk kc+1 loaded to regs (ld.global.cg.v4) while chunk kc computes; STS into
// double-buffered smem A, ONE syncthreads per chunk. Tree grid barrier.
// smem: WsH 0..66048, WsL ..132096, Ah buf0 132096..166912 (hi 17408 + lo 17408),
//       Ah buf1 166912..201728, Gs 201728..209920, Cs ..211968, act ..212992,
//       perm ..213248
#define SMEM2 213248
__global__ __launch_bounds__(256, 1) void k_recurrent(
    const float* __restrict__ W_hh,
    float*       __restrict__ out)
{
    extern __shared__ char dyn[];
    __nv_bfloat16* WsH = (__nv_bfloat16*)(dyn);            //  66048 B (32 x 1032)
    __nv_bfloat16* WsL = (__nv_bfloat16*)(dyn + 66048);    //  66048 B
    float*         Gs  = (float*)(dyn + 201728);           //   8192 B (4 x 64 x 8)
    float*         Cs  = (float*)(dyn + 209920);           //   2048 B (64 x 8)
    int*         s_act = (int*)(dyn + 211968);             //   1024 B
    int*        s_perm = (int*)(dyn + 212992);             //    256 B
    __shared__ unsigned s_base;

    const int tid = threadIdx.x;
    const int cta = blockIdx.x;
    const int hc0 = cta * 8;
    const int wid = tid >> 5, lane = tid & 31;
    const int mw = wid >> 1, nw = wid & 1;

    if (tid < TT) s_act[tid] = g_act[tid];
    if (tid < BB) s_perm[tid] = g_perm[tid];
    if (tid == 0) s_base = *((volatile unsigned*)&g_gen);
    for (int i = tid; i < BB * 8; i += 256) Cs[i] = 0.f;

    // stage W_hh slice hi/lo (rows (q>>3)*H + hc0 + (q&7), q = 0..31)
    for (int v = 0; v < 32; v++) {
        int e = tid + 256 * v;         // 8192 float4s = 32 rows x 256
        int q = e >> 8, c4 = e & 255;
        int gr = (q >> 3) * HH + hc0 + (q & 7);
        float4 w = *(const float4*)&W_hh[(size_t)gr * HH + c4 * 4];
        unsigned h0, l0, h1, l1;
        split_pack(w.x, w.y, h0, l0);
        split_pack(w.z, w.w, h1, l1);
        unsigned idx = q * 516 + c4 * 2;
        ((unsigned*)WsH)[idx]     = h0; ((unsigned*)WsH)[idx + 1] = h1;
        ((unsigned*)WsL)[idx]     = l0; ((unsigned*)WsL)[idx + 1] = l1;
    }

    // zero h parity 0; exactly one u32 per thread chip-wide per plane
    {
        int i = cta * 256 + tid;
        ((unsigned*)g_hh[0])[i] = 0u;
        ((unsigned*)g_hl[0])[i] = 0u;
    }
    __syncthreads();
    unsigned gen = s_base;
    grid_barrier(gen);   // h/c zeroed + visible everywhere

    const int aRow = mw * 16 + (lane & 15);
    const int aCo  = (lane >> 4) << 3;
    const int bRow = nw * 16 + ((lane >> 4) << 3) + (lane & 7);
    const int bCo  = ((lane >> 3) & 1) << 3;
    const int r0   = mw * 16 + (lane >> 2);
    const int jj   = 2 * (lane & 3);

    // per-thread staging slot: e = tid + 256*s, s = 0..7
    //   plane = e>>10 (0 hi / 1 lo), rr = (e>>4)&63, c4 = e&15
    // global u32 idx: rr*512 + kc*64 + c4*4 -> uint4 idx rr*128 + kc*16 + c4
    // smem byte: 132096 + b*34816 + plane*17408 + rr*272 + c4*16
    int s_plane[8], s_rr[8], s_c4[8];
#pragma unroll
    for (int s = 0; s < 8; s++) {
        int e = tid + 256 * s;
        s_plane[s] = e >> 10; s_rr[s] = (e >> 4) & 63; s_c4[s] = e & 15;
    }

    for (int t = 0; t < TT; t++) {
        const int Mact = s_act[t];
        if (Mact == 0) break;            // non-increasing: uniform across CTAs
        const int p = t & 1;
        const bool wact = (mw * 16 < Mact);

        // prefetch gates_x (overlaps whole GEMM)
        float gx[2][4];
        const float* gbase = g_gates + ((size_t)t * BB) * GG;
#pragma unroll
        for (int nt = 0; nt < 2; nt++) {
            int gate = nw * 2 + nt;
            int gcol = gate * HH + hc0 + jj;
            gx[nt][0] = gx[nt][1] = gx[nt][2] = gx[nt][3] = 0.f;
            if (r0 < Mact) {
                float2 v = *(const float2*)(gbase + (size_t)r0 * GG + gcol);
                gx[nt][0] = v.x; gx[nt][1] = v.y;
            }
            if (r0 + 8 < Mact) {
                float2 v = *(const float2*)(gbase + (size_t)(r0 + 8) * GG + gcol);
                gx[nt][2] = v.x; gx[nt][3] = v.y;
            }
        }

        float acc[2][4] = {{0.f,0.f,0.f,0.f},{0.f,0.f,0.f,0.f}};
        const uint4* hh4 = (const uint4*)g_hh[p];
        const uint4* hl4 = (const uint4*)g_hl[p];

        uint4 ra[8], rb[8];
        // load chunk 0 into ra
#pragma unroll
        for (int s = 0; s < 8; s++) {
            ra[s] = (s_rr[s] < Mact)
                ? ldcg4((const unsigned*)((s_plane[s] ? hl4 : hh4) +
                                          (s_rr[s] * 128 + s_c4[s])))
                : make_uint4(0u, 0u, 0u, 0u);
        }

#pragma unroll
        for (int kc = 0; kc < 8; kc++) {       // 8 chunks of 128 k
            uint4* cur = (kc & 1) ? rb : ra;
            uint4* nxt = (kc & 1) ? ra : rb;
            if (kc < 7) {                      // issue loads for kc+1 (overlap)
#pragma unroll
                for (int s = 0; s < 8; s++) {
                    nxt[s] = (s_rr[s] < Mact)
                        ? ldcg4((const unsigned*)((s_plane[s] ? hl4 : hh4) +
                                 (s_rr[s] * 128 + (kc + 1) * 16 + s_c4[s])))
                        : make_uint4(0u, 0u, 0u, 0u);
                }
            }
            // STS chunk kc into buffer kc&1 (WAR safe: sync inside iter kc-1
            // guarantees all warps finished reading this buffer at kc-2)
            {
                char* bufw = dyn + 132096 + (kc & 1) * 34816;
#pragma unroll
                for (int s = 0; s < 8; s++) {
                    *(uint4*)(bufw + s_plane[s] * 17408 + s_rr[s] * 272 +
                              s_c4[s] * 16) = cur[s];
                }
            }
            __syncthreads();
            if (wact) {
                const char* buf = dyn + 132096 + (kc & 1) * 34816;
                const __nv_bfloat16* AhH = (const __nv_bfloat16*)(buf);
                const __nv_bfloat16* AhL = (const __nv_bfloat16*)(buf + 17408);
#pragma unroll
                for (int ks = 0; ks < 8; ks++) {
                    unsigned aH[4], aL[4], bH[4], bL[4];
                    int ac = ks * 16 + aCo;
                    int wc = kc * 128 + ks * 16 + bCo;
                    ldsm4(aH, AhH + aRow * 136 + ac);
                    ldsm4(aL, AhL + aRow * 136 + ac);
                    ldsm4(bH, WsH + bRow * 1032 + wc);
                    ldsm4(bL, WsL + bRow * 1032 + wc);
                    mma16816(acc[0], aH, bH[0], bH[1]);
                    mma16816(acc[1], aH, bH[2], bH[3]);
                    mma16816(acc[0], aH, bL[0], bL[1]);
                    mma16816(acc[1], aH, bL[2], bL[3]);
                    mma16816(acc[0], aL, bH[0], bH[1]);
                    mma16816(acc[1], aL, bH[2], bH[3]);
                }
            }
        }

        // gates -> smem exchange (gate = nw*2 + nt)
        // (Gs region disjoint from Ah buffers; sync below orders it anyway)
#pragma unroll
        for (int nt = 0; nt < 2; nt++) {
            int gate = nw * 2 + nt;
            Gs[(gate * 64 + r0) * 8 + jj]         = acc[nt][0] + gx[nt][0];
            Gs[(gate * 64 + r0) * 8 + jj + 1]     = acc[nt][1] + gx[nt][1];
            Gs[(gate * 64 + r0 + 8) * 8 + jj]     = acc[nt][2] + gx[nt][2];
            Gs[(gate * 64 + r0 + 8) * 8 + jj + 1] = acc[nt][3] + gx[nt][3];
        }
        __syncthreads();

        // CTA-local LSTM update; write h_new hi/lo to next parity
        const int pn = p ^ 1;
        for (int idx = tid; idx < Mact * 8; idx += 256) {
            int m = idx >> 3, j = idx & 7;
            float ig = Gs[(0 * 64 + m) * 8 + j];
            float fg = Gs[(1 * 64 + m) * 8 + j];
            float gg = Gs[(2 * 64 + m) * 8 + j];
            float og = Gs[(3 * 64 + m) * 8 + j];
            float is = 1.f / (1.f + expf(-ig));
            float fs = 1.f / (1.f + expf(-fg));
            float gt = tanhf(gg);
            float os = 1.f / (1.f + expf(-og));
            float cn = fs * Cs[idx] + is * gt;
            Cs[idx] = cn;
            float hn = os * tanhf(cn);
            int col = hc0 + j;
            g_hout[(size_t)m * HH + col] = hn;
            __nv_bfloat16 hh = __float2bfloat16(hn);
            g_hh[pn][m * HH + col] = hh;
            g_hl[pn][m * HH + col] = __float2bfloat16(hn - __bfloat162float(hh));
        }
        grid_barrier(gen);
    }

    // scatter back to original batch order (CTA-owned cols only)
    for (int idx = tid; idx < BB * 8; idx += 256) {
        int m = idx >> 3, j = idx & 7;
        out[(size_t)s_perm[m] * HH + hc0 + j] = g_hout[(size_t)m * HH + hc0 + j];
    }
}

// ---------------- launch --------------------------------------------------------
extern "C" void kernel_launch(void* const* d_in, const int* in_sizes, int n_in,
                              void* d_out, int out_size)
{
    const int*   tokens  = (const int*)  d_in[0];  // int32/int64 autodetected
    const int*   lengths = (const int*)  d_in[1];
    const float* emb     = (const float*)d_in[2];
    const float* W_ih    = (const float*)d_in[3];
    const float* W_hh    = (const float*)d_in[4];
    const float* b_ih    = (const float*)d_in[5];
    const float* b_hh    = (const float*)d_in[6];
    float* out = (float*)d_out;

    cudaFuncSetAttribute(k_input_gemm,
                         cudaFuncAttributeMaxDynamicSharedMemorySize, SMEM1);
    cudaFuncSetAttribute(k_recurrent,
                         cudaFuncAttributeMaxDynamicSharedMemorySize, SMEM2);

    k_prep<<<1, 256>>>(lengths);
    k_wsplit<<<GG / 8, 256>>>(W_ih);                 // 512 CTAs
    k_embed<<<TT * BB / 8, 256>>>(tokens, emb);      // 2048 CTAs

    dim3 g1(GG / 128, TT);                           // (32, 256)
    k_input_gemm<<<g1, 512, SMEM1>>>(b_ih, b_hh);

    k_recurrent<<<NCTA2, 256, SMEM2>>>(W_hh, out);
}